// round 5
// baseline (speedup 1.0000x reference)
#include <cuda_runtime.h>
#include <cuda_bf16.h>

#define MAX_B 16384
#define CHUNK 512
#define SLOT_ITEMS 32

// Scratch for per-segment sums [B, 64] floats (4 MB).
// Invariant: zero at kernel_launch entry. Static init gives first-call zeros;
// finalize re-zeroes each slot after consuming it, restoring the invariant
// for every subsequent (graph-replayed) call.
__device__ float g_scratch[MAX_B * 64];

// Phase 1: balanced gather + segment partial sums.
// 256 threads = 16 slots x 16 lanes. Slot s owns contiguous items
// [blk*CHUNK + 32*s, +32). Lane owns one float4 of the 64-dim row.
__global__ __launch_bounds__(256)
void gather_kernel(const int* __restrict__ offsets,
                   const int* __restrict__ flat_implicit,
                   const float4* __restrict__ imp_emb4,
                   int B, int N) {
    const int t    = threadIdx.x;
    const int lane = t & 15;
    const int slot = t >> 4;

    int j = blockIdx.x * CHUNK + slot * SLOT_ITEMS;
    if (j >= N) return;
    const int run_end = min(j + SLOT_ITEMS, N);

    // Binary search: seg = last b with offsets[b] <= j
    int lo = 0, hi = B;
    while (lo < hi) {
        int mid = (lo + hi) >> 1;
        if (__ldg(&offsets[mid]) <= j) lo = mid + 1; else hi = mid;
    }
    int seg = lo - 1;

    float4 acc = make_float4(0.f, 0.f, 0.f, 0.f);

    for (;;) {
        const int nb   = (seg + 1 < B) ? __ldg(&offsets[seg + 1]) : N;
        const int stop = min(run_end, nb);

        // Hot loop: 8 independent LDG.128 in flight per thread.
        for (; j + 7 < stop; j += 8) {
            const int i0 = __ldg(&flat_implicit[j]);
            const int i1 = __ldg(&flat_implicit[j + 1]);
            const int i2 = __ldg(&flat_implicit[j + 2]);
            const int i3 = __ldg(&flat_implicit[j + 3]);
            const int i4 = __ldg(&flat_implicit[j + 4]);
            const int i5 = __ldg(&flat_implicit[j + 5]);
            const int i6 = __ldg(&flat_implicit[j + 6]);
            const int i7 = __ldg(&flat_implicit[j + 7]);
            const float4 a0 = __ldg(&imp_emb4[(size_t)i0 * 16 + lane]);
            const float4 a1 = __ldg(&imp_emb4[(size_t)i1 * 16 + lane]);
            const float4 a2 = __ldg(&imp_emb4[(size_t)i2 * 16 + lane]);
            const float4 a3 = __ldg(&imp_emb4[(size_t)i3 * 16 + lane]);
            const float4 a4 = __ldg(&imp_emb4[(size_t)i4 * 16 + lane]);
            const float4 a5 = __ldg(&imp_emb4[(size_t)i5 * 16 + lane]);
            const float4 a6 = __ldg(&imp_emb4[(size_t)i6 * 16 + lane]);
            const float4 a7 = __ldg(&imp_emb4[(size_t)i7 * 16 + lane]);
            acc.x += ((a0.x + a1.x) + (a2.x + a3.x)) + ((a4.x + a5.x) + (a6.x + a7.x));
            acc.y += ((a0.y + a1.y) + (a2.y + a3.y)) + ((a4.y + a5.y) + (a6.y + a7.y));
            acc.z += ((a0.z + a1.z) + (a2.z + a3.z)) + ((a4.z + a5.z) + (a6.z + a7.z));
            acc.w += ((a0.w + a1.w) + (a2.w + a3.w)) + ((a4.w + a5.w) + (a6.w + a7.w));
        }
        for (; j < stop; ++j) {
            const float4 a = __ldg(&imp_emb4[(size_t)__ldg(&flat_implicit[j]) * 16 + lane]);
            acc.x += a.x; acc.y += a.y; acc.z += a.z; acc.w += a.w;
        }

        // Flush this segment's partial sum (fire-and-forget red.global).
        float* dst = g_scratch + (size_t)seg * 64 + lane * 4;
        atomicAdd(dst + 0, acc.x);
        atomicAdd(dst + 1, acc.y);
        atomicAdd(dst + 2, acc.z);
        atomicAdd(dst + 3, acc.w);

        if (stop >= run_end) break;
        acc = make_float4(0.f, 0.f, 0.f, 0.f);
        // Advance past boundary (skip empty/duplicate segments).
        seg++;
        while (seg + 1 < B && __ldg(&offsets[seg + 1]) <= j) seg++;
    }
}

// Phase 2: finalize. 16 rows per 256-thread CTA; 16 lanes per row.
// Also re-zeroes the scratch slot it consumed (keeps entry invariant).
__global__ __launch_bounds__(256)
void finalize_kernel(const int* __restrict__ user_ids,
                     const int* __restrict__ item_ids,
                     const int* __restrict__ offsets,
                     const float4* __restrict__ user_emb4,
                     const float4* __restrict__ item_emb4,
                     const float* __restrict__ user_bias,
                     const float* __restrict__ item_bias,
                     const float* __restrict__ global_bias,
                     float* __restrict__ out,
                     int B, int N) {
    const int t    = threadIdx.x;
    const int lane = t & 15;
    const int r    = blockIdx.x * 16 + (t >> 4);
    if (r >= B) return;

    const int start = __ldg(&offsets[r]);
    const int end   = (r + 1 < B) ? __ldg(&offsets[r + 1]) : N;
    const int len   = end - start;
    const float invnorm = (len > 0) ? rsqrtf((float)len) : 1.0f;

    float4* srow = reinterpret_cast<float4*>(g_scratch) + (size_t)r * 16 + lane;
    const float4 sum = *srow;
    *srow = make_float4(0.f, 0.f, 0.f, 0.f);   // restore zero invariant

    const int u  = __ldg(&user_ids[r]);
    const int it = __ldg(&item_ids[r]);
    const float4 u4 = __ldg(&user_emb4[(size_t)u * 16 + lane]);
    const float4 i4 = __ldg(&item_emb4[(size_t)it * 16 + lane]);

    float dot = (u4.x + sum.x * invnorm) * i4.x
              + (u4.y + sum.y * invnorm) * i4.y
              + (u4.z + sum.z * invnorm) * i4.z
              + (u4.w + sum.w * invnorm) * i4.w;

    #pragma unroll
    for (int off = 8; off > 0; off >>= 1)
        dot += __shfl_down_sync(0xffffffffu, dot, off, 16);

    if (lane == 0)
        out[r] = dot + __ldg(&user_bias[u]) + __ldg(&item_bias[it]) + __ldg(&global_bias[0]);
}

extern "C" void kernel_launch(void* const* d_in, const int* in_sizes, int n_in,
                              void* d_out, int out_size) {
    const int*    user_ids      = (const int*)d_in[0];
    const int*    item_ids      = (const int*)d_in[1];
    const int*    offsets       = (const int*)d_in[2];
    const int*    flat_implicit = (const int*)d_in[3];
    const float4* user_emb4     = (const float4*)d_in[4];
    const float4* item_emb4     = (const float4*)d_in[5];
    const float4* imp_emb4      = (const float4*)d_in[6];
    const float*  user_bias     = (const float*)d_in[7];
    const float*  item_bias     = (const float*)d_in[8];
    const float*  global_bias   = (const float*)d_in[9];
    float*        out           = (float*)d_out;

    const int B = in_sizes[0];          // 16384
    const int N = in_sizes[3];          // 819200

    gather_kernel<<<(N + CHUNK - 1) / CHUNK, 256>>>(offsets, flat_implicit,
                                                    imp_emb4, B, N);

    finalize_kernel<<<(B + 15) / 16, 256>>>(user_ids, item_ids, offsets,
                                            user_emb4, item_emb4,
                                            user_bias, item_bias, global_bias,
                                            out, B, N);
}

// round 6
// speedup vs baseline: 1.1455x; 1.1455x over previous
#include <cuda_runtime.h>
#include <cuda_bf16.h>

// Fused: one 256-thread CTA per batch row. 16 item-slots x 16 lanes.
// Each lane owns one float4 (16B) of the 256B embedding row.

__global__ __launch_bounds__(256)
void svdpp_kernel(const int* __restrict__ user_ids,
                  const int* __restrict__ item_ids,
                  const int* __restrict__ offsets,
                  const int* __restrict__ flat_implicit,
                  const float4* __restrict__ user_emb4,
                  const float4* __restrict__ item_emb4,
                  const float4* __restrict__ imp_emb4,
                  const float* __restrict__ user_bias,
                  const float* __restrict__ item_bias,
                  const float* __restrict__ global_bias,
                  float* __restrict__ out,
                  int B, int N) {
    const int b    = blockIdx.x;
    const int t    = threadIdx.x;
    const int lane = t & 15;            // which float4 of the row
    const int slot = t >> 4;            // item slot 0..15
    const int warp = t >> 5;            // 0..7

    const int start = __ldg(&offsets[b]);
    const int end   = (b + 1 < B) ? __ldg(&offsets[b + 1]) : N;
    const int len   = end - start;

    float4 acc = make_float4(0.f, 0.f, 0.f, 0.f);

    int j = start + slot;
    // Main: 4 independent row loads in flight (slot stride 16).
    for (; j + 48 < end; j += 64) {
        const int i0 = __ldg(&flat_implicit[j]);
        const int i1 = __ldg(&flat_implicit[j + 16]);
        const int i2 = __ldg(&flat_implicit[j + 32]);
        const int i3 = __ldg(&flat_implicit[j + 48]);
        const float4 a0 = __ldg(&imp_emb4[(size_t)i0 * 16 + lane]);
        const float4 a1 = __ldg(&imp_emb4[(size_t)i1 * 16 + lane]);
        const float4 a2 = __ldg(&imp_emb4[(size_t)i2 * 16 + lane]);
        const float4 a3 = __ldg(&imp_emb4[(size_t)i3 * 16 + lane]);
        acc.x += (a0.x + a1.x) + (a2.x + a3.x);
        acc.y += (a0.y + a1.y) + (a2.y + a3.y);
        acc.z += (a0.z + a1.z) + (a2.z + a3.z);
        acc.w += (a0.w + a1.w) + (a2.w + a3.w);
    }
    // Mid: 2 loads in flight.
    for (; j + 16 < end; j += 32) {
        const int i0 = __ldg(&flat_implicit[j]);
        const int i1 = __ldg(&flat_implicit[j + 16]);
        const float4 a0 = __ldg(&imp_emb4[(size_t)i0 * 16 + lane]);
        const float4 a1 = __ldg(&imp_emb4[(size_t)i1 * 16 + lane]);
        acc.x += a0.x + a1.x;
        acc.y += a0.y + a1.y;
        acc.z += a0.z + a1.z;
        acc.w += a0.w + a1.w;
    }
    if (j < end) {
        const float4 a = __ldg(&imp_emb4[(size_t)__ldg(&flat_implicit[j]) * 16 + lane]);
        acc.x += a.x; acc.y += a.y; acc.z += a.z; acc.w += a.w;
    }

    // Combine slot pair within each warp (slots 2w and 2w+1).
    acc.x += __shfl_xor_sync(0xffffffffu, acc.x, 16);
    acc.y += __shfl_xor_sync(0xffffffffu, acc.y, 16);
    acc.z += __shfl_xor_sync(0xffffffffu, acc.z, 16);
    acc.w += __shfl_xor_sync(0xffffffffu, acc.w, 16);

    // Cross-warp combine: 8 warps x 16 lanes of float4.
    __shared__ float4 s[8][16];
    if ((t & 31) < 16) s[warp][lane] = acc;
    __syncthreads();

    if (t < 16) {
        float4 sum = s[0][t];
        #pragma unroll
        for (int w = 1; w < 8; ++w) {
            const float4 o = s[w][t];
            sum.x += o.x; sum.y += o.y; sum.z += o.z; sum.w += o.w;
        }

        const float invnorm = (len > 0) ? rsqrtf((float)len) : 1.0f;
        const int u  = __ldg(&user_ids[b]);
        const int it = __ldg(&item_ids[b]);

        const float4 u4 = __ldg(&user_emb4[(size_t)u * 16 + t]);
        const float4 i4 = __ldg(&item_emb4[(size_t)it * 16 + t]);

        float dot = (u4.x + sum.x * invnorm) * i4.x
                  + (u4.y + sum.y * invnorm) * i4.y
                  + (u4.z + sum.z * invnorm) * i4.z
                  + (u4.w + sum.w * invnorm) * i4.w;

        #pragma unroll
        for (int off = 8; off > 0; off >>= 1)
            dot += __shfl_down_sync(0x0000ffffu, dot, off);

        if (t == 0)
            out[b] = dot + __ldg(&user_bias[u]) + __ldg(&item_bias[it])
                         + __ldg(&global_bias[0]);
    }
}

extern "C" void kernel_launch(void* const* d_in, const int* in_sizes, int n_in,
                              void* d_out, int out_size) {
    const int*    user_ids      = (const int*)d_in[0];
    const int*    item_ids      = (const int*)d_in[1];
    const int*    offsets       = (const int*)d_in[2];
    const int*    flat_implicit = (const int*)d_in[3];
    const float4* user_emb4     = (const float4*)d_in[4];
    const float4* item_emb4     = (const float4*)d_in[5];
    const float4* imp_emb4      = (const float4*)d_in[6];
    const float*  user_bias     = (const float*)d_in[7];
    const float*  item_bias     = (const float*)d_in[8];
    const float*  global_bias   = (const float*)d_in[9];
    float*        out           = (float*)d_out;

    const int B = in_sizes[0];          // 16384
    const int N = in_sizes[3];          // 819200

    svdpp_kernel<<<B, 256>>>(user_ids, item_ids, offsets, flat_implicit,
                             user_emb4, item_emb4, imp_emb4,
                             user_bias, item_bias, global_bias,
                             out, B, N);
}